// round 17
// baseline (speedup 1.0000x reference)
#include <cuda_runtime.h>
#include <cuda_bf16.h>
#include <math.h>

// Problem constants (fixed by the dataset).
#define NN 50000
#define DD 256
#define KK 64
#define HH 8
#define OO 64
#define EE 1600000
#define HK (HH*KK)   // 512
#define NB 196       // ceil(NN/256)

// ---------------- scratch (device globals; no allocation allowed) ----------
__device__ __nv_bfloat16  g_Wct [HK*DD];            // (layer_W@Wall)^T bf16 [512,256]
__device__ float          g_bc  [HK];               // layer_b @ Wall
__device__ __nv_bfloat16  g_xb  [(size_t)NN*DD];    // x in bf16 (25.6MB)
__device__ __nv_bfloat16  g_eWtT[OO*HK];            // end_W^T bf16 [64,512]
__device__ __nv_bfloat16  g_hallb[(size_t)NN*HK];   // per-head features 51.2MB
__device__ __nv_bfloat16  g_out1b[(size_t)NN*HK];   // aggregated + elu, bf16
__device__ int   g_deg [NN];
__device__ int   g_excl[NN];
__device__ int   g_part[256];
__device__ int   g_rowptr[NN+1];
__device__ int   g_off [NN];
__device__ int   g_srt [EE];                // src ids sorted by dst (CSR)
__device__ float g_ssrc[NN*HH];             // accumulated by mma1 epilogue
__device__ float g_sdst[NN*HH];
__device__ float          g_h2 [NN*OO];     // fp32 (score projection)
__device__ __nv_bfloat16  g_h2b[NN*OO];     // bf16 (gathers)
__device__ float g_s2s [NN];
__device__ float g_s2d [NN];
__device__ int   g_edges_is64;

// ---------------- helpers ---------------------------------------------------
__device__ __forceinline__ float lrelu(float x) { return x > 0.f ? x : 0.2f * x; }
__device__ __forceinline__ float elu(float x)   { return x > 0.f ? x : expm1f(x); }
__device__ __forceinline__ unsigned smem_u32(const void* p) {
    return (unsigned)__cvta_generic_to_shared(p);
}
__device__ __forceinline__ void cp16(unsigned dst, const void* src, int nbytes) {
    asm volatile("cp.async.cg.shared.global [%0], [%1], 16, %2;"
                 :: "r"(dst), "l"(src), "r"(nbytes));
}
__device__ __forceinline__ void cp_commit() { asm volatile("cp.async.commit_group;"); }
__device__ __forceinline__ void cp_wait1()  { asm volatile("cp.async.wait_group 1;" ::: "memory"); }

__device__ __forceinline__ void unpack8(uint4 u, float* v) {
    float2 p;
    p = __bfloat1622float2(*(__nv_bfloat162*)&u.x); v[0] = p.x; v[1] = p.y;
    p = __bfloat1622float2(*(__nv_bfloat162*)&u.y); v[2] = p.x; v[3] = p.y;
    p = __bfloat1622float2(*(__nv_bfloat162*)&u.z); v[4] = p.x; v[5] = p.y;
    p = __bfloat1622float2(*(__nv_bfloat162*)&u.w); v[6] = p.x; v[7] = p.y;
}

// read edge endpoints straight from the raw (int32-or-int64) input buffer
__device__ __forceinline__ int edge_src(const void* ed, int i) {
    int s = g_edges_is64 ? (int)((const long long*)ed)[i] : ((const int*)ed)[i];
    return min(max(s, 0), NN - 1);
}
__device__ __forceinline__ int edge_dst(const void* ed, int i) {
    int d = g_edges_is64 ? (int)((const long long*)ed)[(size_t)EE + i]
                         : ((const int*)ed)[EE + i];
    return min(max(d, 0), NN - 1);
}

// ---------------- prep kernels -----------------------------------------------
// x -> bf16; also zeroes the proj accumulators (side branch, pre-mma1)
__global__ void k_cvt_xb(const float* __restrict__ x) {
    size_t i = (size_t)blockIdx.x * 256 + threadIdx.x;   // one per 8 elems
    if (i < NN*HH) { g_ssrc[i] = 0.f; g_sdst[i] = 0.f; }
    if (i * 8 >= (size_t)NN*DD) return;
    float4 v0 = ((const float4*)x)[i*2];
    float4 v1 = ((const float4*)x)[i*2 + 1];
    uint4 o;
    *(__nv_bfloat162*)&o.x = __floats2bfloat162_rn(v0.x, v0.y);
    *(__nv_bfloat162*)&o.y = __floats2bfloat162_rn(v0.z, v0.w);
    *(__nv_bfloat162*)&o.z = __floats2bfloat162_rn(v1.x, v1.y);
    *(__nv_bfloat162*)&o.w = __floats2bfloat162_rn(v1.z, v1.w);
    ((uint4*)g_xb)[i] = o;
}

// Wct[j][i] = (layer_W @ heads_W_packed)[i][j] bf16; block DD does bc.
// Wall[k][j] == hw[(j>>6)*DD*KK + k*KK + (j&63)] indexed directly (no pack pass).
__global__ void k_combine_W(const float* __restrict__ W1, const float* __restrict__ b,
                            const float* __restrict__ hw) {
    __shared__ float row[DD];
    int i = blockIdx.x;            // 0..DD (DD = bias row)
    int j = threadIdx.x;           // 0..511
    const float* src = (i < DD) ? &W1[i*DD] : b;
    for (int k = j; k < DD; k += 512) row[k] = src[k];
    __syncthreads();
    const float* wp = hw + (size_t)(j >> 6)*DD*KK + (j & 63);
    float acc = 0.f;
    for (int k = 0; k < DD; k++) acc = fmaf(row[k], wp[k*KK], acc);
    if (i < DD) g_Wct[j*DD + i] = __float2bfloat16(acc);
    else        g_bc[j] = acc;
}

// end_W^T -> bf16 [OO, HK]
__global__ void k_cvt_ewT(const float* __restrict__ w) {
    int i = blockIdx.x * 256 + threadIdx.x;     // i < HK*OO
    if (i < HK*OO) {
        int k = i >> 6, o = i & 63;
        g_eWtT[o*HK + k] = __float2bfloat16(w[i]);
    }
}

// ---------------- bf16 MMA GEMM: C[M,N] = A[M,K] @ Bt[N,K]^T (+bias) ----------
// A row-major bf16, Bt n-major bf16. m16n8k16, 3-stage cp.async.
// OUT: 0 fp32, 1 bf16, 2 both. PROJ: also accumulate attention projections
// (s_src/s_dst) into g_ssrc/g_sdst via quad-reduce + atomics (GEMM1 only).
template<int BN, bool BIAS, int OUT, bool PROJ>
__global__ __launch_bounds__(256, 2)
void k_mmabf(int M, int N, int K,
             const __nv_bfloat16* __restrict__ A, const __nv_bfloat16* __restrict__ Bt,
             const float* __restrict__ bias, const float* __restrict__ ha,
             float* __restrict__ Cf, __nv_bfloat16* __restrict__ Cb)
{
    constexpr int BM_ = 128, BK_ = 32;
    constexpr int ASTRH = 40;          // halves; banks conflict-free
    constexpr int BSTRH = 40;
    constexpr int ASZH = BM_ * ASTRH;
    constexpr int BSZH = BN * BSTRH;
    constexpr int STSZ = ASZH + BSZH;  // halves per stage
    constexpr int WN = BN / 4;
    constexpr int NI = WN / 8;
    constexpr int BLD = (BN * 4) / 256;

    extern __shared__ __nv_bfloat16 smh[];   // [3][STSZ]

    const int tid  = threadIdx.x;
    const int lane = tid & 31;
    const int wid  = tid >> 5;
    const int wm = wid & 1, wn = wid >> 1;
    const int g = lane >> 2, tg = lane & 3;

    const int bm0 = blockIdx.y * BM_;
    const int bn0 = blockIdx.x * BN;

    float acc[4][NI][4];
    #pragma unroll
    for (int mi = 0; mi < 4; mi++)
        #pragma unroll
        for (int ni = 0; ni < NI; ni++)
            #pragma unroll
            for (int q = 0; q < 4; q++) acc[mi][ni][q] = 0.f;

    auto load_stage = [&](int kt, int buf) {
        int k0 = kt * BK_;
        __nv_bfloat16* Asb = smh + buf*STSZ;
        __nv_bfloat16* Bsb = Asb + ASZH;
        #pragma unroll
        for (int it = 0; it < 2; it++) {
            int i = tid + it*256;
            int row = i >> 2, c = (i & 3) * 8;
            int gr = bm0 + row;
            const __nv_bfloat16* src = A + (size_t)min(gr, M-1)*K + k0 + c;
            cp16(smem_u32(Asb + row*ASTRH + c), src, (gr < M) ? 16 : 0);
        }
        #pragma unroll
        for (int it = 0; it < BLD; it++) {
            int i = tid + it*256;
            int row = i >> 2, c = (i & 3) * 8;
            const __nv_bfloat16* src = Bt + (size_t)(bn0 + row)*K + k0 + c;
            cp16(smem_u32(Bsb + row*BSTRH + c), src, 16);
        }
        cp_commit();
    };

    const int nkt = K / BK_;                // >= 3 for both call sites
    load_stage(0, 0);
    load_stage(1, 1);
    cp_wait1();
    __syncthreads();

    for (int kt = 0; kt < nkt; kt++) {
        int cur = kt % 3;
        if (kt + 2 < nkt) load_stage(kt + 2, (kt + 2) % 3);
        const __nv_bfloat162* As2 = (const __nv_bfloat162*)(smh + cur*STSZ);
        const __nv_bfloat162* Bs2 = (const __nv_bfloat162*)(smh + cur*STSZ + ASZH);
        #pragma unroll
        for (int ks = 0; ks < 2; ks++) {
            int base = ks*8 + tg;
            unsigned a[4][4];
            #pragma unroll
            for (int mi = 0; mi < 4; mi++) {
                int r = wm*64 + mi*16 + g;
                a[mi][0] = *(const unsigned*)&As2[r*20 + base];
                a[mi][1] = *(const unsigned*)&As2[(r+8)*20 + base];
                a[mi][2] = *(const unsigned*)&As2[r*20 + base + 4];
                a[mi][3] = *(const unsigned*)&As2[(r+8)*20 + base + 4];
            }
            unsigned b[NI][2];
            #pragma unroll
            for (int ni = 0; ni < NI; ni++) {
                int c = wn*WN + ni*8 + g;
                b[ni][0] = *(const unsigned*)&Bs2[c*20 + base];
                b[ni][1] = *(const unsigned*)&Bs2[c*20 + base + 4];
            }
            #pragma unroll
            for (int mi = 0; mi < 4; mi++)
                #pragma unroll
                for (int ni = 0; ni < NI; ni++)
                    asm volatile(
                        "mma.sync.aligned.m16n8k16.row.col.f32.bf16.bf16.f32 "
                        "{%0,%1,%2,%3}, {%4,%5,%6,%7}, {%8,%9}, {%0,%1,%2,%3};"
                        : "+f"(acc[mi][ni][0]), "+f"(acc[mi][ni][1]),
                          "+f"(acc[mi][ni][2]), "+f"(acc[mi][ni][3])
                        : "r"(a[mi][0]), "r"(a[mi][1]), "r"(a[mi][2]), "r"(a[mi][3]),
                          "r"(b[ni][0]), "r"(b[ni][1]));
        }
        cp_wait1();
        __syncthreads();
    }

    // ---- epilogue: store (+bias) and optional fused attention projection ----
    int head = 0;
    float asv[NI*2], adv[NI*2], psrc[8], pdst[8];
    if (PROJ) {
        head = (bn0 + wn*WN) >> 6;           // warp spans one head's half
        #pragma unroll
        for (int ni = 0; ni < NI; ni++) {
            int cc = (wn*WN + ni*8 + tg*2) & 63;
            asv[ni*2+0] = ha[head*128 + cc];
            asv[ni*2+1] = ha[head*128 + cc + 1];
            adv[ni*2+0] = ha[head*128 + 64 + cc];
            adv[ni*2+1] = ha[head*128 + 64 + cc + 1];
        }
        #pragma unroll
        for (int q = 0; q < 8; q++) { psrc[q] = 0.f; pdst[q] = 0.f; }
    }

    #pragma unroll
    for (int mi = 0; mi < 4; mi++) {
        #pragma unroll
        for (int ni = 0; ni < NI; ni++) {
            int gr = bm0 + wm*64 + mi*16 + g;
            int gc = bn0 + wn*WN + ni*8 + tg*2;
            float bx = 0.f, by = 0.f;
            if (BIAS) { bx = bias[gc]; by = bias[gc+1]; }
            float v0 = acc[mi][ni][0] + bx, v1 = acc[mi][ni][1] + by;
            float v2 = acc[mi][ni][2] + bx, v3 = acc[mi][ni][3] + by;
            if (gr < M) {
                if (OUT != 1) *(float2*)&Cf[(size_t)gr*N + gc] = make_float2(v0, v1);
                if (OUT >= 1) ((__nv_bfloat162*)Cb)[((size_t)gr*N + gc) >> 1]
                                  = __floats2bfloat162_rn(v0, v1);
            }
            if (gr + 8 < M) {
                if (OUT != 1) *(float2*)&Cf[(size_t)(gr+8)*N + gc] = make_float2(v2, v3);
                if (OUT >= 1) ((__nv_bfloat162*)Cb)[((size_t)(gr+8)*N + gc) >> 1]
                                  = __floats2bfloat162_rn(v2, v3);
            }
            if (PROJ) {
                psrc[mi*2+0] += v0*asv[ni*2] + v1*asv[ni*2+1];
                pdst[mi*2+0] += v0*adv[ni*2] + v1*adv[ni*2+1];
                psrc[mi*2+1] += v2*asv[ni*2] + v3*asv[ni*2+1];
                pdst[mi*2+1] += v2*adv[ni*2] + v3*adv[ni*2+1];
            }
        }
    }

    if (PROJ) {
        #pragma unroll
        for (int mi = 0; mi < 4; mi++) {
            #pragma unroll
            for (int rh = 0; rh < 2; rh++) {
                float s = psrc[mi*2+rh], d = pdst[mi*2+rh];
                s += __shfl_xor_sync(0xffffffffu, s, 1);
                s += __shfl_xor_sync(0xffffffffu, s, 2);
                d += __shfl_xor_sync(0xffffffffu, d, 1);
                d += __shfl_xor_sync(0xffffffffu, d, 2);
                int gr = bm0 + wm*64 + mi*16 + g + rh*8;
                if (tg == 0 && gr < M) {
                    atomicAdd(&g_ssrc[gr*8 + head], s);
                    atomicAdd(&g_sdst[gr*8 + head], d);
                }
            }
        }
    }
}

// ---------------- CSR build ----------------------------------------------------
__global__ void k_init(const unsigned* __restrict__ raw) {
    int i = blockIdx.x * 256 + threadIdx.x;
    if (i < NN) g_deg[i] = 0;
    if (blockIdx.x == 0) {
        __shared__ int nz;
        if (threadIdx.x == 0) nz = 0;
        __syncthreads();
        for (int k = threadIdx.x; k < 2048; k += 256)
            if (raw[2*k + 1] != 0u) atomicOr(&nz, 1);
        __syncthreads();
        if (threadIdx.x == 0) g_edges_is64 = (nz == 0) ? 1 : 0;
    }
}

__global__ void k_hist(const void* __restrict__ ed) {
    int i = blockIdx.x * 256 + threadIdx.x;
    if (i >= EE) return;
    atomicAdd(&g_deg[edge_dst(ed, i)], 1);
}

__global__ void k_scan1() {
    __shared__ int sh[256];
    int t = threadIdx.x;
    int n = blockIdx.x * 256 + t;
    int v = (n < NN) ? g_deg[n] : 0;
    sh[t] = v;
    __syncthreads();
    #pragma unroll
    for (int off = 1; off < 256; off <<= 1) {
        int x = (t >= off) ? sh[t - off] : 0;
        __syncthreads();
        sh[t] += x;
        __syncthreads();
    }
    if (n < NN) g_excl[n] = sh[t] - v;
    if (t == 255) g_part[blockIdx.x] = sh[255];
}
__global__ void k_scan2() {
    __shared__ int sh[256];
    int t = threadIdx.x;
    int v = (t < NB) ? g_part[t] : 0;
    sh[t] = v;
    __syncthreads();
    #pragma unroll
    for (int off = 1; off < 256; off <<= 1) {
        int x = (t >= off) ? sh[t - off] : 0;
        __syncthreads();
        sh[t] += x;
        __syncthreads();
    }
    g_part[t] = sh[t] - v;   // exclusive
}
__global__ void k_scan3() {
    int n = blockIdx.x * 256 + threadIdx.x;
    if (n < NN) {
        int r = g_excl[n] + g_part[n >> 8];
        g_rowptr[n] = r;
        g_off[n] = r;
    }
    if (n == 0) g_rowptr[NN] = EE;
}

__global__ void k_scatter(const void* __restrict__ ed) {
    int i = blockIdx.x * 256 + threadIdx.x;
    if (i >= EE) return;
    int s = edge_src(ed, i);
    int d = edge_dst(ed, i);
    int pos = atomicAdd(&g_off[d], 1);
    g_srt[pos] = s;
}

// ---------------- layer-2 score projection ------------------------------------
__global__ void k_proj_end(const float* __restrict__ ea) {
    int w = threadIdx.x >> 5, l = threadIdx.x & 31;
    int n = blockIdx.x * 8 + w;
    if (n >= NN) return;
    const float* row = g_h2 + (size_t)n*OO;
    float x0 = row[l], x1 = row[l+32];
    float s = x0*ea[l]    + x1*ea[l+32];
    float d = x0*ea[64+l] + x1*ea[96+l];
    #pragma unroll
    for (int off = 16; off; off >>= 1) {
        s += __shfl_xor_sync(0xffffffffu, s, off);
        d += __shfl_xor_sync(0xffffffffu, d, off);
    }
    if (l == 0) { g_s2s[n] = s; g_s2d[n] = d; }
}

// ---------------- layer-1 fused softmax + aggregation (single pass) -----------
// No max-subtraction (scores O(±7), exp safe). Denominator accumulated in the
// same serial edge loop (weights are lane-uniform per head pair).
__global__ void k_fused1() {
    int w = threadIdx.x >> 5, lane = threadIdx.x & 31;
    int n = blockIdx.x * 8 + w;
    if (n >= NN) return;
    int r0 = g_rowptr[n], r1 = g_rowptr[n+1];

    const int h0 = lane >> 3, h1 = h0 + 4;
    float sd0 = g_sdst[n*8 + h0];
    float sd1 = g_sdst[n*8 + h1];

    float acc0[8], acc1[8];
    #pragma unroll
    for (int j = 0; j < 8; j++) { acc0[j] = 0.f; acc1[j] = 0.f; }
    float wsum0 = 0.f, wsum1 = 0.f;

    int i = r0;
    for (; i + 4 <= r1; i += 4) {
        int s0 = g_srt[i], s1 = g_srt[i+1], s2 = g_srt[i+2], s3 = g_srt[i+3];
        float t0 = g_ssrc[s0*8 + h0], q0 = g_ssrc[s0*8 + h1];
        float t1 = g_ssrc[s1*8 + h0], q1 = g_ssrc[s1*8 + h1];
        float t2 = g_ssrc[s2*8 + h0], q2 = g_ssrc[s2*8 + h1];
        float t3 = g_ssrc[s3*8 + h0], q3 = g_ssrc[s3*8 + h1];
        const uint4* rp0 = (const uint4*)(g_hallb + (size_t)s0 * HK);
        const uint4* rp1 = (const uint4*)(g_hallb + (size_t)s1 * HK);
        const uint4* rp2 = (const uint4*)(g_hallb + (size_t)s2 * HK);
        const uint4* rp3 = (const uint4*)(g_hallb + (size_t)s3 * HK);
        uint4 ua0 = rp0[lane], ub0 = rp0[lane + 32];
        uint4 ua1 = rp1[lane], ub1 = rp1[lane + 32];
        uint4 ua2 = rp2[lane], ub2 = rp2[lane + 32];
        uint4 ua3 = rp3[lane], ub3 = rp3[lane + 32];
        float w00 = __expf(lrelu(t0 + sd0)), w01 = __expf(lrelu(q0 + sd1));
        float w10 = __expf(lrelu(t1 + sd0)), w11 = __expf(lrelu(q1 + sd1));
        float w20 = __expf(lrelu(t2 + sd0)), w21 = __expf(lrelu(q2 + sd1));
        float w30 = __expf(lrelu(t3 + sd0)), w31 = __expf(lrelu(q3 + sd1));
        wsum0 += (w00 + w10) + (w20 + w30);
        wsum1 += (w01 + w11) + (w21 + w31);
        float v[8];
        unpack8(ua0, v);
        #pragma unroll
        for (int j = 0; j < 8; j++) acc0[j] = fmaf(w00, v[j], acc0[j]);
        unpack8(ub0, v);
        #pragma unroll
        for (int j = 0; j < 8; j++) acc1[j] = fmaf(w01, v[j], acc1[j]);
        unpack8(ua1, v);
        #pragma unroll
        for (int j = 0; j < 8; j++) acc0[j] = fmaf(w10, v[j], acc0[j]);
        unpack8(ub1, v);
        #pragma unroll
        for (int j = 0; j < 8; j++) acc1[j] = fmaf(w11, v[j], acc1[j]);
        unpack8(ua2, v);
        #pragma unroll
        for (int j = 0; j < 8; j++) acc0[j] = fmaf(w20, v[j], acc0[j]);
        unpack8(ub2, v);
        #pragma unroll
        for (int j = 0; j < 8; j++) acc1[j] = fmaf(w21, v[j], acc1[j]);
        unpack8(ua3, v);
        #pragma unroll
        for (int j = 0; j < 8; j++) acc0[j] = fmaf(w30, v[j], acc0[j]);
        unpack8(ub3, v);
        #pragma unroll
        for (int j = 0; j < 8; j++) acc1[j] = fmaf(w31, v[j], acc1[j]);
    }
    for (; i < r1; i++) {
        int s = g_srt[i];
        float w0 = __expf(lrelu(g_ssrc[s*8 + h0] + sd0));
        float w1 = __expf(lrelu(g_ssrc[s*8 + h1] + sd1));
        wsum0 += w0; wsum1 += w1;
        const uint4* rp = (const uint4*)(g_hallb + (size_t)s * HK);
        uint4 u0 = rp[lane], u1 = rp[lane + 32];
        float v[8];
        unpack8(u0, v);
        #pragma unroll
        for (int j = 0; j < 8; j++) acc0[j] = fmaf(w0, v[j], acc0[j]);
        unpack8(u1, v);
        #pragma unroll
        for (int j = 0; j < 8; j++) acc1[j] = fmaf(w1, v[j], acc1[j]);
    }

    float dinv0 = 1.f / (wsum0 + 1e-16f);
    float dinv1 = 1.f / (wsum1 + 1e-16f);

    __nv_bfloat16* orow = g_out1b + (size_t)n * HK;
    uint4 o;
    *(__nv_bfloat162*)&o.x = __floats2bfloat162_rn(elu(acc0[0]*dinv0), elu(acc0[1]*dinv0));
    *(__nv_bfloat162*)&o.y = __floats2bfloat162_rn(elu(acc0[2]*dinv0), elu(acc0[3]*dinv0));
    *(__nv_bfloat162*)&o.z = __floats2bfloat162_rn(elu(acc0[4]*dinv0), elu(acc0[5]*dinv0));
    *(__nv_bfloat162*)&o.w = __floats2bfloat162_rn(elu(acc0[6]*dinv0), elu(acc0[7]*dinv0));
    *(uint4*)&orow[8*lane] = o;
    *(__nv_bfloat162*)&o.x = __floats2bfloat162_rn(elu(acc1[0]*dinv1), elu(acc1[1]*dinv1));
    *(__nv_bfloat162*)&o.y = __floats2bfloat162_rn(elu(acc1[2]*dinv1), elu(acc1[3]*dinv1));
    *(__nv_bfloat162*)&o.z = __floats2bfloat162_rn(elu(acc1[4]*dinv1), elu(acc1[5]*dinv1));
    *(__nv_bfloat162*)&o.w = __floats2bfloat162_rn(elu(acc1[6]*dinv1), elu(acc1[7]*dinv1));
    *(uint4*)&orow[256 + 8*lane] = o;
}

// ---------------- layer-2 fused agg + elu + row softmax (single pass) ---------
__global__ void k_fused2(float* __restrict__ out) {
    int w = threadIdx.x >> 5, lane = threadIdx.x & 31;
    int n = blockIdx.x * 8 + w;
    if (n >= NN) return;
    int r0 = g_rowptr[n], r1 = g_rowptr[n+1];
    float sd = g_s2d[n];

    const __nv_bfloat162* hb = (const __nv_bfloat162*)g_h2b;
    float2 acc = make_float2(0.f, 0.f);
    float wsum = 0.f;
    int i = r0;
    for (; i + 4 <= r1; i += 4) {
        int s0 = g_srt[i], s1 = g_srt[i+1], s2 = g_srt[i+2], s3 = g_srt[i+3];
        float t0 = g_s2s[s0], t1 = g_s2s[s1], t2 = g_s2s[s2], t3 = g_s2s[s3];
        float2 v0 = __bfloat1622float2(hb[(size_t)s0*32 + lane]);
        float2 v1 = __bfloat1622float2(hb[(size_t)s1*32 + lane]);
        float2 v2 = __bfloat1622float2(hb[(size_t)s2*32 + lane]);
        float2 v3 = __bfloat1622float2(hb[(size_t)s3*32 + lane]);
        float w0 = __expf(lrelu(t0 + sd));
        float w1 = __expf(lrelu(t1 + sd));
        float w2 = __expf(lrelu(t2 + sd));
        float w3 = __expf(lrelu(t3 + sd));
        wsum += (w0 + w1) + (w2 + w3);
        acc.x = fmaf(w0, v0.x, acc.x); acc.y = fmaf(w0, v0.y, acc.y);
        acc.x = fmaf(w1, v1.x, acc.x); acc.y = fmaf(w1, v1.y, acc.y);
        acc.x = fmaf(w2, v2.x, acc.x); acc.y = fmaf(w2, v2.y, acc.y);
        acc.x = fmaf(w3, v3.x, acc.x); acc.y = fmaf(w3, v3.y, acc.y);
    }
    for (; i < r1; i++) {
        int s = g_srt[i];
        float wt = __expf(lrelu(g_s2s[s] + sd));
        wsum += wt;
        float2 v = __bfloat1622float2(hb[(size_t)s*32 + lane]);
        acc.x = fmaf(wt, v.x, acc.x); acc.y = fmaf(wt, v.y, acc.y);
    }
    float dinv = 1.f / (wsum + 1e-16f);

    float x0 = elu(acc.x * dinv);
    float x1 = elu(acc.y * dinv);
    float mx = fmaxf(x0, x1);
    #pragma unroll
    for (int off = 16; off; off >>= 1)
        mx = fmaxf(mx, __shfl_xor_sync(0xffffffffu, mx, off));
    float e0 = __expf(x0 - mx), e1 = __expf(x1 - mx);
    float ssum = e0 + e1;
    #pragma unroll
    for (int off = 16; off; off >>= 1)
        ssum += __shfl_xor_sync(0xffffffffu, ssum, off);
    float inv = 1.f / ssum;
    *(float2*)&out[(size_t)n*OO + 2*lane] = make_float2(e0 * inv, e1 * inv);
}

// ---------------- driver ------------------------------------------------------
extern "C" void kernel_launch(void* const* d_in, const int* in_sizes, int n_in,
                              void* d_out, int out_size) {
    const float* x       = (const float*)d_in[0];
    const void*  edges   = d_in[1];
    const float* layer_W = (const float*)d_in[2];
    const float* layer_b = (const float*)d_in[3];
    const float* heads_W = (const float*)d_in[4];
    const float* heads_a = (const float*)d_in[5];
    const float* end_W   = (const float*)d_in[6];
    const float* end_a   = (const float*)d_in[7];
    float*       out     = (float*)d_out;

    float *p_bc, *p_h2;
    __nv_bfloat16 *p_xb, *p_Wct, *p_eWtT, *p_hallb, *p_out1b, *p_h2b;
    cudaGetSymbolAddress((void**)&p_bc,    g_bc);
    cudaGetSymbolAddress((void**)&p_xb,    g_xb);
    cudaGetSymbolAddress((void**)&p_Wct,   g_Wct);
    cudaGetSymbolAddress((void**)&p_eWtT,  g_eWtT);
    cudaGetSymbolAddress((void**)&p_hallb, g_hallb);
    cudaGetSymbolAddress((void**)&p_out1b, g_out1b);
    cudaGetSymbolAddress((void**)&p_h2,    g_h2);
    cudaGetSymbolAddress((void**)&p_h2b,   g_h2b);

    constexpr int SMEM1 = 3*(128*40 + 128*40)*2;  // 61440 B
    constexpr int SMEM2 = 3*(128*40 + 64*40)*2;   // 46080 B
    cudaFuncSetAttribute((const void*)k_mmabf<128,true,1,true>,
                         cudaFuncAttributeMaxDynamicSharedMemorySize, SMEM1);
    cudaFuncSetAttribute((const void*)k_mmabf<64,false,2,false>,
                         cudaFuncAttributeMaxDynamicSharedMemorySize, SMEM2);

    // --- fork a side branch (handles intentionally not destroyed; no device
    //     memory is allocated by stream/event creation) -----------------------
    cudaStream_t sB;
    cudaStreamCreateWithFlags(&sB, cudaStreamNonBlocking);
    cudaEvent_t evFork, evX, evJoin;
    cudaEventCreateWithFlags(&evFork, cudaEventDisableTiming);
    cudaEventCreateWithFlags(&evX,    cudaEventDisableTiming);
    cudaEventCreateWithFlags(&evJoin, cudaEventDisableTiming);
    cudaEventRecord(evFork, 0);
    cudaStreamWaitEvent(sB, evFork, 0);

    // side branch: x->bf16 + zero proj accumulators, then CSR build + end_W^T
    k_cvt_xb<<<(int)(((size_t)NN*DD/8 + 255)/256), 256, 0, sB>>>(x);
    cudaEventRecord(evX, sB);
    k_init<<<NB, 256, 0, sB>>>((const unsigned*)edges);
    k_hist<<<(EE + 255)/256, 256, 0, sB>>>(edges);
    k_scan1<<<NB, 256, 0, sB>>>();
    k_scan2<<<1, 256, 0, sB>>>();
    k_scan3<<<NB, 256, 0, sB>>>();
    k_scatter<<<(EE + 255)/256, 256, 0, sB>>>(edges);
    k_cvt_ewT<<<(HK*OO + 255)/256, 256, 0, sB>>>(end_W);
    cudaEventRecord(evJoin, sB);

    // main branch: combined weights, then GEMM1 with fused projection epilogue
    k_combine_W<<<DD + 1, 512>>>(layer_W, layer_b, heads_W);
    cudaStreamWaitEvent(0, evX, 0);   // xb + zeroed ssrc/sdst ready
    {   // hall = x @ Wc + bc -> bf16; also s_src/s_dst via epilogue atomics
        dim3 grid(HK/128, (NN + 127)/128);
        k_mmabf<128,true,1,true><<<grid, 256, SMEM1>>>(NN, HK, DD, p_xb, p_Wct,
                                                       p_bc, heads_a,
                                                       nullptr, p_hallb);
    }

    // join: fused1 needs CSR (side) + hall/scores (main)
    cudaStreamWaitEvent(0, evJoin, 0);

    // --- layer 1: fused softmax + aggregation (all 8 heads, single pass) -----
    k_fused1<<<(NN + 7)/8, 256>>>();

    // --- h2 = out1 @ end_W -> fp32 + bf16   [50000,512]x[512,64] -------------
    {
        dim3 grid(1, (NN + 127)/128);
        k_mmabf<64,false,2,false><<<grid, 256, SMEM2>>>(NN, OO, HK, p_out1b,
                                                        p_eWtT, nullptr, nullptr,
                                                        p_h2, p_h2b);
    }

    // --- layer 2: projection + fused single-pass agg/elu/row-softmax ---------
    k_proj_end<<<(NN + 7)/8, 256>>>(end_a);
    k_fused2<<<(NN + 7)/8, 256>>>(out);
}